// round 12
// baseline (speedup 1.0000x reference)
#include <cuda_runtime.h>
#include <cuda_fp16.h>
#include <math.h>
#include <stdint.h>

// ---------------- problem constants ----------------
#define B_ 512
#define D_ 512
#define C_ 100000
#define NTILE 3128   // 4 m-tiles x 782 n-tiles

#define S_F    30.0f
#define COSM_F 0.8775825618903728f
#define SINM_F 0.479425538604203f
#define TH_F  (-0.8775825618903728f)
#define MM_F   0.2397127693021015f

// ---------------- device scratch ----------------
__device__ __half g_Xh[B_ * D_];
__device__ __half g_Wh[(size_t)C_ * D_];
__device__ int g_label[B_];

// ---------------- helpers ----------------
__device__ __forceinline__ uint32_t smem_u32(const void* p) {
    uint32_t a;
    asm("{ .reg .u64 t; cvta.to.shared.u64 t, %1; cvt.u32.u64 %0, t; }" : "=r"(a) : "l"(p));
    return a;
}

#define CP16(sm, gp, sz) \
    asm volatile("cp.async.cg.shared.global [%0], [%1], 16, %2;" \
                 :: "r"(sm), "l"(gp), "r"(sz) : "memory")

#define LDSM4(r, addr) \
    asm volatile("ldmatrix.sync.aligned.m8n8.x4.shared.b16 {%0,%1,%2,%3}, [%4];" \
                 : "=r"((r)[0]), "=r"((r)[1]), "=r"((r)[2]), "=r"((r)[3]) : "r"(addr))

#define MMA(acc, a, b) \
    asm volatile("mma.sync.aligned.m16n8k16.row.col.f32.f16.f16.f32 " \
                 "{%0,%1,%2,%3},{%4,%5,%6,%7},{%8,%9},{%0,%1,%2,%3};" \
                 : "+f"((acc)[0]), "+f"((acc)[1]), "+f"((acc)[2]), "+f"((acc)[3]) \
                 : "r"((a)[0]), "r"((a)[1]), "r"((a)[2]), "r"((a)[3]), \
                   "r"((b)[0]), "r"((b)[1]))

__device__ __forceinline__ uint32_t h2u(__half2 h) {
    return *reinterpret_cast<uint32_t*>(&h);
}

__device__ __forceinline__ float arcf(float c, bool isl) {
    c = fminf(1.0f, fmaxf(-1.0f, c));
    float s2 = fminf(1.0f, fmaxf(1e-9f, 1.0f - c * c));
    float sn;
    asm("sqrt.approx.f32 %0, %1;" : "=f"(sn) : "f"(s2));
    float phi = c * COSM_F - sn * SINM_F;
    phi = (c > TH_F) ? phi : (c - MM_F);
    return (isl ? phi : c) * S_F;
}

// ---------------- X: normalize + fp16 convert + label decode ----------------
__global__ void xprep_kernel(const float* __restrict__ X, const int* __restrict__ raw) {
    int row = blockIdx.x;
    int t = threadIdx.x;  // 128
    const float4* xf = reinterpret_cast<const float4*>(X + (size_t)row * D_);
    float4 v = xf[t];
    float s = v.x * v.x + v.y * v.y + v.z * v.z + v.w * v.w;
#pragma unroll
    for (int o = 16; o > 0; o >>= 1) s += __shfl_xor_sync(0xffffffffu, s, o);
    __shared__ float ws[4];
    if ((t & 31) == 0) ws[t >> 5] = s;
    __syncthreads();
    float tot = ws[0] + ws[1] + ws[2] + ws[3];
    float inv = 1.0f / fmaxf(sqrtf(tot), 1e-12f);
    uint2 hv;
    hv.x = h2u(__floats2half2_rn(v.x * inv, v.y * inv));
    hv.y = h2u(__floats2half2_rn(v.z * inv, v.w * inv));
    *reinterpret_cast<uint2*>(g_Xh + (size_t)row * D_ + t * 4) = hv;

    // label decode: int64 layout iff first 8 odd int32 words are all zero
    if (t == 0) {
        int odd = raw[1] | raw[3] | raw[5] | raw[7] | raw[9] | raw[11] | raw[13] | raw[15];
        g_label[row] = (odd == 0) ? raw[2 * row] : raw[row];
    }
}

// ---------------- W: normalize + fp16 convert (2 rows per block) ----------
__global__ __launch_bounds__(256)
void wprep_kernel(const float* __restrict__ W) {
    int h = threadIdx.x >> 7;
    int t = threadIdx.x & 127;
    int row = blockIdx.x * 2 + h;      // C_ even -> always valid
    const float4* wf = reinterpret_cast<const float4*>(W + (size_t)row * D_);
    float4 v = wf[t];
    float s = v.x * v.x + v.y * v.y + v.z * v.z + v.w * v.w;
#pragma unroll
    for (int o = 16; o > 0; o >>= 1) s += __shfl_xor_sync(0xffffffffu, s, o);
    __shared__ float ws[8];
    if ((t & 31) == 0) ws[h * 4 + (t >> 5)] = s;
    __syncthreads();
    float tot = ws[h * 4 + 0] + ws[h * 4 + 1] + ws[h * 4 + 2] + ws[h * 4 + 3];
    float inv = 1.0f / fmaxf(sqrtf(tot), 1e-12f);
    uint2 hv;
    hv.x = h2u(__floats2half2_rn(v.x * inv, v.y * inv));
    hv.y = h2u(__floats2half2_rn(v.z * inv, v.w * inv));
    *reinterpret_cast<uint2*>(g_Wh + (size_t)row * D_ + t * 4) = hv;
}

// ---------------- persistent GEMM + ArcFace ----------------
// R4 tile config (128x128, BK=64, 3-stage, 2 CTAs/SM); each CTA strides
// over tiles with a continuous cross-tile pipeline (no per-tile drain).
#define A_OFF 0
#define B_OFF 16384
#define STAGE_SZ 32768
#define SMEM_TOTAL (3 * STAGE_SZ)   // 98304

__global__ __launch_bounds__(256, 2)
void arcface_mma_kernel(float* __restrict__ out) {
    extern __shared__ char Smem[];
    const uint32_t sb = smem_u32(Smem);
    const int tid = threadIdx.x;
    const int lane = tid & 31;
    const int wid = tid >> 5;
    const int step = gridDim.x;
    const int mW = (wid >> 2) * 64;    // warp tile 64x32
    const int nW = (wid & 3) * 32;

    float acc[4][4][4];
#pragma unroll
    for (int i = 0; i < 4; i++)
#pragma unroll
        for (int j = 0; j < 4; j++)
#pragma unroll
            for (int q = 0; q < 4; q++) acc[i][j][q] = 0.0f;

    // ldmatrix lane-address components
    const int arow = mW + (lane & 7) + ((lane >> 3) & 1) * 8;   // + 16*i
    const int acol = ((lane >> 4) & 1) * 16;                    // + 32*g
    const int brow = nW + ((lane >> 4) & 1) * 8 + (lane & 7);   // + 16*jp
    const int bcol = ((lane >> 3) & 1) * 16;
    const int sx   = (lane & 7) * 16;                           // swizzle xor

    // tile t: m0 = (t & 3)*128 (m fastest -> 4 m-tiles share W n-tile), n0 = (t>>2)*128
    auto load_stage = [&](int t, int kc, int st) {
        const int m0 = (t & 3) * 128;
        const int n0 = (t >> 2) * 128;
        uint32_t base = sb + st * STAGE_SZ;
#pragma unroll
        for (int j = 0; j < 4; j++) {
            int idx = tid + 256 * j;
            int r = idx >> 3, c = idx & 7;
            uint32_t doff = (uint32_t)(r * 128 + ((c * 16) ^ ((r & 7) * 16)));
            size_t abyt = (size_t)(m0 + r) * (D_ * 2) + kc * 128 + c * 16;
            CP16(base + A_OFF + doff, (const char*)g_Xh + abyt, 16);
            int n = n0 + r;
            int ok = (n < C_) ? 16 : 0;
            int nn = (n < C_) ? n : 0;
            size_t bbyt = (size_t)nn * (D_ * 2) + kc * 128 + c * 16;
            CP16(base + B_OFF + doff, (const char*)g_Wh + bbyt, ok);
        }
    };

    auto compute_stage = [&](int st) {
        const uint32_t Ab = sb + st * STAGE_SZ + A_OFF;
        const uint32_t Bb = sb + st * STAGE_SZ + B_OFF;
#pragma unroll
        for (int g = 0; g < 4; g++) {
            uint32_t bh[4][2];
#pragma unroll
            for (int jp = 0; jp < 2; jp++) {
                uint32_t boff = (uint32_t)((brow + 16 * jp) * 128 + ((g * 32 + bcol) ^ sx));
                uint32_t t4[4];
                LDSM4(t4, Bb + boff);
                bh[2 * jp][0] = t4[0]; bh[2 * jp][1] = t4[1];
                bh[2 * jp + 1][0] = t4[2]; bh[2 * jp + 1][1] = t4[3];
            }
#pragma unroll
            for (int i = 0; i < 4; i++) {
                uint32_t a4[4];
                uint32_t aoff = (uint32_t)((arow + 16 * i) * 128 + ((g * 32 + acol) ^ sx));
                LDSM4(a4, Ab + aoff);
#pragma unroll
                for (int j = 0; j < 4; j++) MMA(acc[i][j], a4, bh[j]);
            }
        }
    };

    // ---- prologue: first 3 chunks of this CTA's first tile ----
    int ti = blockIdx.x;
    load_stage(ti, 0, 0);
    asm volatile("cp.async.commit_group;" ::: "memory");
    load_stage(ti, 1, 1);
    asm volatile("cp.async.commit_group;" ::: "memory");
    load_stage(ti, 2, 2);
    asm volatile("cp.async.commit_group;" ::: "memory");

    // ---- persistent loop: continuous pipeline across tiles ----
    int stC = 0;   // stage of the chunk being computed (= global chunk % 3)
    for (; ti < NTILE; ti += step) {
        const int m0 = (ti & 3) * 128;
        const int n0 = (ti >> 2) * 128;
        for (int kc = 0; kc < 8; kc++) {
            asm volatile("cp.async.wait_group 2;" ::: "memory");
            __syncthreads();
            compute_stage(stC);
            __syncthreads();
            int lt = ti, lk = kc + 3;
            if (lk >= 8) { lt += step; lk -= 8; }
            if (lt < NTILE) load_stage(lt, lk, stC);
            asm volatile("cp.async.commit_group;" ::: "memory");
            stC = (stC == 2) ? 0 : stC + 1;
        }

        // ---- per-tile epilogue (next tile's loads are in flight) ----
#pragma unroll
        for (int i = 0; i < 4; i++) {
            int gm = m0 + mW + i * 16 + (lane >> 2);
            int lab0 = g_label[gm];
            int lab1 = g_label[gm + 8];
#pragma unroll
            for (int j = 0; j < 4; j++) {
                int col = n0 + nW + j * 8 + (lane & 3) * 2;
                if (col < C_) {   // C_ even -> pair stays in-bounds together
                    float2 v0, v1;
                    v0.x = arcf(acc[i][j][0], col == lab0);
                    v0.y = arcf(acc[i][j][1], col + 1 == lab0);
                    v1.x = arcf(acc[i][j][2], col == lab1);
                    v1.y = arcf(acc[i][j][3], col + 1 == lab1);
                    *reinterpret_cast<float2*>(out + (size_t)gm * C_ + col) = v0;
                    *reinterpret_cast<float2*>(out + (size_t)(gm + 8) * C_ + col) = v1;
                }
#pragma unroll
                for (int q = 0; q < 4; q++) acc[i][j][q] = 0.0f;
            }
        }
    }
}

// ---------------- launch ----------------
extern "C" void kernel_launch(void* const* d_in, const int* in_sizes, int n_in,
                              void* d_out, int out_size) {
    const float* X = nullptr;
    const float* W = nullptr;
    const void*  L = nullptr;

    for (int i = 0; i < n_in; i++) {
        int s = in_sizes[i];
        if (s == B_ * D_)      X = (const float*)d_in[i];
        else if (s == C_ * D_) W = (const float*)d_in[i];
        else if (s == B_)      L = d_in[i];
    }
    if (!X) X = (const float*)d_in[0];
    if (!L) L = d_in[1];
    if (!W) W = (const float*)d_in[2];

    float* out = (float*)d_out;

    xprep_kernel<<<B_, 128>>>(X, (const int*)L);
    wprep_kernel<<<C_ / 2, 256>>>(W);

    int dev = 0, sms = 148;
    cudaGetDevice(&dev);
    cudaDeviceGetAttribute(&sms, cudaDevAttrMultiProcessorCount, dev);

    cudaFuncSetAttribute(arcface_mma_kernel,
                         cudaFuncAttributeMaxDynamicSharedMemorySize, SMEM_TOTAL);
    arcface_mma_kernel<<<2 * sms, 256, SMEM_TOTAL>>>(out);
    (void)out_size;
}